// round 16
// baseline (speedup 1.0000x reference)
#include <cuda_runtime.h>
#include <cuda_bf16.h>
#include <math.h>
#include <stdint.h>

#define BB 16
#define TDEC 256
#define TSRC 512
#define EE 1024
#define HH 1024
#define DH 64
#define NBLK 128

// ---------------- scratch (static device memory; no allocations) -------------
__device__ float g_gx[BB * TDEC * 4 * HH];
__device__ float g_hseq[BB * TDEC * HH];
__device__ __nv_bfloat16 g_hb[2][2][BB][HH];
__device__ float g_biascomb[4 * HH];
__device__ float g_Kb[BB * TSRC * EE];
__device__ float g_Vb[BB * TSRC * EE];
__device__ float g_Kb2[BB * TSRC * EE];
__device__ float g_Vb2[BB * TSRC * EE];
__device__ float g_Qb[BB * TDEC * EE];
__device__ float g_Qb2[BB * TDEC * EE];
__device__ unsigned g_bar;

// bf16 hi/lo split buffers (main stream)
__device__ __nv_bfloat16 c_bigA_hi[BB * TDEC * EE];
__device__ __nv_bfloat16 c_bigA_lo[BB * TDEC * EE];
__device__ __nv_bfloat16 c_Wih_hi[4 * HH * EE];
__device__ __nv_bfloat16 c_Wih_lo[4 * HH * EE];
__device__ __nv_bfloat16 c_hseq_hi[BB * TDEC * HH];
__device__ __nv_bfloat16 c_hseq_lo[BB * TDEC * HH];
__device__ __nv_bfloat16 c_AO_hi[BB * TDEC * EE];
__device__ __nv_bfloat16 c_AO_lo[BB * TDEC * EE];
__device__ __nv_bfloat16 c_AO2_hi[BB * TDEC * EE];
__device__ __nv_bfloat16 c_AO2_lo[BB * TDEC * EE];
// side-stream buffers
__device__ __nv_bfloat16 c_enc_hi[BB * TSRC * EE];
__device__ __nv_bfloat16 c_enc_lo[BB * TSRC * EE];
__device__ __nv_bfloat16 c_W2_hi[EE * EE];
__device__ __nv_bfloat16 c_W2_lo[EE * EE];
__device__ __nv_bfloat16 c_W3_hi[EE * EE];
__device__ __nv_bfloat16 c_W3_lo[EE * EE];
// dedicated Q/O weight splits (produced on s2 during the scan)
__device__ __nv_bfloat16 c_Wq0_hi[EE * EE];
__device__ __nv_bfloat16 c_Wq0_lo[EE * EE];
__device__ __nv_bfloat16 c_Wq1_hi[EE * EE];
__device__ __nv_bfloat16 c_Wq1_lo[EE * EE];
__device__ __nv_bfloat16 c_Wo0_hi[EE * EE];
__device__ __nv_bfloat16 c_Wo0_lo[EE * EE];
__device__ __nv_bfloat16 c_Wo1_hi[EE * EE];
__device__ __nv_bfloat16 c_Wo1_lo[EE * EE];

// ---------------- f32x2 packed-fp32 helpers ----------------------------------
__device__ __forceinline__ unsigned long long pack2(float a, float b) {
    unsigned long long r;
    asm("mov.b64 %0, {%1,%2};" : "=l"(r) : "f"(a), "f"(b));
    return r;
}
__device__ __forceinline__ void fma2(unsigned long long& d,
                                     unsigned long long a, unsigned long long b) {
    asm("fma.rn.f32x2 %0, %1, %2, %0;" : "+l"(d) : "l"(a), "l"(b));
}
__device__ __forceinline__ void mul2(unsigned long long& d, unsigned long long a) {
    asm("mul.rn.f32x2 %0, %0, %1;" : "+l"(d) : "l"(a));
}
__device__ __forceinline__ float2 unpack2(unsigned long long v) {
    float2 r;
    asm("mov.b64 {%0,%1}, %2;" : "=f"(r.x), "=f"(r.y) : "l"(v));
    return r;
}

__device__ __forceinline__ uint32_t smem_u32(const void* p) {
    uint32_t a;
    asm("{ .reg .u64 t; cvta.to.shared.u64 t, %1; cvt.u32.u64 %0, t; }"
        : "=r"(a) : "l"(p));
    return a;
}

// ---------------- mma helpers --------------------------------------------------
__device__ __forceinline__ void ldsm4(uint32_t* r, uint32_t addr) {
    asm volatile("ldmatrix.sync.aligned.m8n8.x4.shared.b16 {%0,%1,%2,%3}, [%4];"
                 : "=r"(r[0]), "=r"(r[1]), "=r"(r[2]), "=r"(r[3]) : "r"(addr));
}
__device__ __forceinline__ void mma16816(float* c, const uint32_t* a,
                                         uint32_t b0, uint32_t b1) {
    asm volatile(
        "mma.sync.aligned.m16n8k16.row.col.f32.bf16.bf16.f32 "
        "{%0,%1,%2,%3}, {%4,%5,%6,%7}, {%8,%9}, {%0,%1,%2,%3};"
        : "+f"(c[0]), "+f"(c[1]), "+f"(c[2]), "+f"(c[3])
        : "r"(a[0]), "r"(a[1]), "r"(a[2]), "r"(a[3]), "r"(b0), "r"(b1));
}

// ---------------- conv kernels -------------------------------------------------
__global__ void conv_split_kernel(const float* __restrict__ src,
                                  __nv_bfloat16* __restrict__ hi,
                                  __nv_bfloat16* __restrict__ lo, int n4) {
    int i = blockIdx.x * 256 + threadIdx.x;
    if (i >= n4) return;
    float4 v = ((const float4*)src)[i];
    float a[4] = {v.x, v.y, v.z, v.w};
    unsigned short h[4], l[4];
#pragma unroll
    for (int j = 0; j < 4; j++) {
        __nv_bfloat16 hb = __float2bfloat16(a[j]);
        __nv_bfloat16 lb = __float2bfloat16(a[j] - __bfloat162float(hb));
        h[j] = *(unsigned short*)&hb;
        l[j] = *(unsigned short*)&lb;
    }
    ((ushort4*)hi)[i] = make_ushort4(h[0], h[1], h[2], h[3]);
    ((ushort4*)lo)[i] = make_ushort4(l[0], l[1], l[2], l[3]);
}

// fused head conv: blocks [0,4096) split X; blocks [4096,8192) split Wih (+bias)
__global__ void conv_head_kernel(const float* __restrict__ X,
                                 __nv_bfloat16* __restrict__ Xhi,
                                 __nv_bfloat16* __restrict__ Xlo,
                                 const float* __restrict__ Wih,
                                 __nv_bfloat16* __restrict__ Whi,
                                 __nv_bfloat16* __restrict__ Wlo,
                                 const float* __restrict__ bih,
                                 const float* __restrict__ bhh) {
    int blk = blockIdx.x;
    const float* src;
    __nv_bfloat16 *hi, *lo;
    int i;
    if (blk < 4096) {
        src = X; hi = Xhi; lo = Xlo;
        i = blk * 256 + threadIdx.x;
    } else {
        src = Wih; hi = Whi; lo = Wlo;
        i = (blk - 4096) * 256 + threadIdx.x;
        if (blk - 4096 < 16) {
            int bi = (blk - 4096) * 256 + threadIdx.x;
            g_biascomb[bi] = bih[bi] + bhh[bi];
        }
    }
    float4 v = ((const float4*)src)[i];
    float a[4] = {v.x, v.y, v.z, v.w};
    unsigned short h[4], l[4];
#pragma unroll
    for (int j = 0; j < 4; j++) {
        __nv_bfloat16 hb = __float2bfloat16(a[j]);
        __nv_bfloat16 lb = __float2bfloat16(a[j] - __bfloat162float(hb));
        h[j] = *(unsigned short*)&hb;
        l[j] = *(unsigned short*)&lb;
    }
    ((ushort4*)hi)[i] = make_ushort4(h[0], h[1], h[2], h[3]);
    ((ushort4*)lo)[i] = make_ushort4(l[0], l[1], l[2], l[3]);
}

// ---------------- tensor-core GEMM via mma.sync (3-stage, 1 sync/chunk) -------
#define KC 64
#define MATB (128 * 72 * 2)
#define STAGEB (4 * MATB)
#define NSTAGE 3

__device__ __forceinline__ void gemm_body(
    const __nv_bfloat16* __restrict__ Ahi, const __nv_bfloat16* __restrict__ Alo,
    const __nv_bfloat16* __restrict__ Whi, const __nv_bfloat16* __restrict__ Wlo,
    const float* __restrict__ bias,
    const float* __restrict__ add, int addstride,
    float* __restrict__ out, int ostride, int m0, int n0, float* smf) {
    const uint32_t smb = smem_u32(smf);
    const int tid = threadIdx.x;
    const int warp = tid >> 5, lane = tid & 31;
    const int wm = warp >> 1, wn = warp & 1;
    const __nv_bfloat16* srcs[4] = {Ahi, Alo, Whi, Wlo};
    const int matoff[4] = {0, MATB, 2 * MATB, 3 * MATB};

    auto issue = [&](int c) {
        uint32_t sb = smb + (c % NSTAGE) * STAGEB;
#pragma unroll
        for (int i = 0; i < 16; i++) {
            int idx = tid + i * 256;
            int mat = idx >> 10;
            int rem = idx & 1023;
            int r = rem >> 3;
            int j = rem & 7;
            const __nv_bfloat16* g =
                srcs[mat] + (size_t)((mat < 2 ? m0 : n0) + r) * 1024 + c * KC + j * 8;
            uint32_t s = sb + matoff[mat] + r * 144 + j * 16;
            asm volatile("cp.async.cg.shared.global [%0], [%1], 16;"
                         :: "r"(s), "l"(g));
        }
        asm volatile("cp.async.commit_group;");
    };

    float acc[2][8][4];
#pragma unroll
    for (int mt = 0; mt < 2; mt++)
#pragma unroll
        for (int nt = 0; nt < 8; nt++)
#pragma unroll
            for (int e = 0; e < 4; e++) acc[mt][nt][e] = 0.f;

    const int a_row = lane & 15, a_kg = lane >> 4;
    const int b_row = (lane & 7) + ((lane & 16) >> 1);
    const int b_kg = (lane >> 3) & 1;

    issue(0);
    issue(1);
    for (int c = 0; c < 16; c++) {
        if (c < 15) {
            asm volatile("cp.async.wait_group 1;");
        } else {
            asm volatile("cp.async.wait_group 0;");
        }
        __syncthreads();

        if (c + 2 < 16) issue(c + 2);

        uint32_t st = smb + (c % NSTAGE) * STAGEB;
#pragma unroll
        for (int ks = 0; ks < 4; ks++) {
            uint32_t ah[2][4], al[2][4], wh[4][4], wl[4][4];
#pragma unroll
            for (int mt = 0; mt < 2; mt++) {
                uint32_t ra = st + (wm * 32 + mt * 16 + a_row) * 144 +
                              ks * 32 + a_kg * 16;
                ldsm4(ah[mt], ra);
                ldsm4(al[mt], ra + MATB);
            }
#pragma unroll
            for (int np = 0; np < 4; np++) {
                uint32_t rb = st + 2 * MATB + (wn * 64 + np * 16 + b_row) * 144 +
                              ks * 32 + b_kg * 16;
                ldsm4(wh[np], rb);
                ldsm4(wl[np], rb + MATB);
            }
#pragma unroll
            for (int mt = 0; mt < 2; mt++)
#pragma unroll
                for (int nt = 0; nt < 8; nt++) {
                    int np = nt >> 1, hf = (nt & 1) * 2;
                    mma16816(acc[mt][nt], ah[mt], wh[np][hf], wh[np][hf + 1]);
                    mma16816(acc[mt][nt], ah[mt], wl[np][hf], wl[np][hf + 1]);
                    mma16816(acc[mt][nt], al[mt], wh[np][hf], wh[np][hf + 1]);
                }
        }
    }

    const int q = lane >> 2, p = lane & 3;
#pragma unroll
    for (int mt = 0; mt < 2; mt++) {
#pragma unroll
        for (int nt = 0; nt < 8; nt++) {
            int n = n0 + wn * 64 + nt * 8 + p * 2;
            float b0 = bias[n], b1 = bias[n + 1];
#pragma unroll
            for (int half = 0; half < 2; half++) {
                int m = m0 + wm * 32 + mt * 16 + q + half * 8;
                float2 r;
                r.x = acc[mt][nt][half * 2 + 0] + b0;
                r.y = acc[mt][nt][half * 2 + 1] + b1;
                if (add) {
                    const float* ap = &add[(size_t)m * addstride + n];
                    r.x += ap[0]; r.y += ap[1];
                }
                *(float2*)&out[(size_t)m * ostride + n] = r;
            }
        }
    }
}

__global__ void __launch_bounds__(256, 1)
gemm_mma_kernel(const __nv_bfloat16* __restrict__ Ahi,
                const __nv_bfloat16* __restrict__ Alo,
                const __nv_bfloat16* __restrict__ Whi,
                const __nv_bfloat16* __restrict__ Wlo,
                const float* __restrict__ bias,
                const float* __restrict__ add, int addstride,
                float* __restrict__ out, int ostride) {
    extern __shared__ float smf[];
    gemm_body(Ahi, Alo, Whi, Wlo, bias, add, addstride, out, ostride,
              blockIdx.y * 128, blockIdx.x * 128, smf);
}

__global__ void __launch_bounds__(256, 1)
gemm_xproj_kernel(const __nv_bfloat16* __restrict__ Ahi,
                  const __nv_bfloat16* __restrict__ Alo,
                  const __nv_bfloat16* __restrict__ Whi,
                  const __nv_bfloat16* __restrict__ Wlo,
                  const float* __restrict__ bias,
                  float* __restrict__ out) {
    extern __shared__ float smf[];
    if (blockIdx.x == 0 && blockIdx.y == 0) {
        for (int i = threadIdx.x; i < 8192; i += 256)
            ((uint4*)g_hb)[i] = make_uint4(0, 0, 0, 0);
        if (threadIdx.x == 0) g_bar = 0u;
    }
    gemm_body(Ahi, Alo, Whi, Wlo, bias, nullptr, 0, out, 4096,
              blockIdx.y * 128, blockIdx.x * 128, smf);
}

__global__ void __launch_bounds__(256, 1)
gemm_dual_kernel(const __nv_bfloat16* __restrict__ Ahi,
                 const __nv_bfloat16* __restrict__ Alo,
                 const __nv_bfloat16* __restrict__ W1hi,
                 const __nv_bfloat16* __restrict__ W1lo,
                 const float* __restrict__ b1, float* __restrict__ o1,
                 const __nv_bfloat16* __restrict__ W2hi,
                 const __nv_bfloat16* __restrict__ W2lo,
                 const float* __restrict__ b2, float* __restrict__ o2) {
    extern __shared__ float smf[];
    int bx = blockIdx.x;
    if (bx < 8)
        gemm_body(Ahi, Alo, W1hi, W1lo, b1, nullptr, 0, o1, EE,
                  blockIdx.y * 128, bx * 128, smf);
    else
        gemm_body(Ahi, Alo, W2hi, W2lo, b2, nullptr, 0, o2, EE,
                  blockIdx.y * 128, (bx - 8) * 128, smf);
}

// ---------------- persistent LSTM scan (tensor-core, W register-resident) -----
#define WROWB 2064
#define SM_WH 0
#define SM_WL 66048
#define SM_HH 132096
#define SM_HL 165120
#define SM_RED 198144
#define SM_STAGE 201216            // 512 B h-staging (inside old red region tail)
#define SM_GS 204288
#define SM_CS 206336
#define LSTM_SMEM_B 206848

__global__ void __launch_bounds__(256, 1) lstm_scan_kernel(
    const float* __restrict__ Whh, float* __restrict__ out) {
    extern __shared__ float smf[];
    char* smbyte = (char*)smf;
    const uint32_t smb = smem_u32(smf);
    float* red = (float*)(smbyte + SM_RED);
    unsigned short* stg = (unsigned short*)(smbyte + SM_STAGE);
    float* gsf = (float*)(smbyte + SM_GS);
    float* cs  = (float*)(smbyte + SM_CS);

    const int tid = threadIdx.x;
    const int bk = blockIdx.x;
    const int warp = tid >> 5, lane = tid & 31;
    const int mt = warp >> 2, kq = warp & 3;
    unsigned* pbar = &g_bar;

    for (int idx = tid; idx < 32 * 1024; idx += 256) {
        int r = idx >> 10, k = idx & 1023;
        int grow = (r & 3) * 1024 + bk * 8 + (r >> 2);
        float w = Whh[(size_t)grow * 1024 + k];
        __nv_bfloat16 hb = __float2bfloat16(w);
        __nv_bfloat16 lb = __float2bfloat16(w - __bfloat162float(hb));
        ((__nv_bfloat16*)(smbyte + SM_WH))[r * 1032 + k] = hb;
        ((__nv_bfloat16*)(smbyte + SM_WL))[r * 1032 + k] = lb;
    }
    if (tid < 128) cs[tid] = 0.f;
    __syncthreads();

    const uint32_t a_base = smb + SM_WH +
        (mt * 16 + (lane & 15)) * WROWB + (lane >> 4) * 16;
    const uint32_t b_base = smb + SM_HH +
        ((lane & 7) + ((lane & 16) >> 1)) * WROWB + ((lane >> 3) & 1) * 16;

    uint32_t wfh[16][4], wfl[16][4];
#pragma unroll
    for (int kc = 0; kc < 16; kc++) {
        uint32_t koff = kq * 512 + kc * 32;
        ldsm4(wfh[kc], a_base + koff);
        ldsm4(wfl[kc], a_base + koff + (SM_WL - SM_WH));
    }

    const int ul = tid >> 4, bb = tid & 15;
    const int u = bk * 8 + ul;

    for (int t = 0; t < TDEC; t++) {
        float gx0 = 0.f, gx1 = 0.f, gx2 = 0.f, gx3 = 0.f;
        if (tid < 128) {
            size_t xb = ((size_t)(bb * TDEC + t)) * 4096 + u;
            gx0 = g_gx[xb];
            gx1 = g_gx[xb + 1024];
            gx2 = g_gx[xb + 2048];
            gx3 = g_gx[xb + 3072];
        }

        const char* srcb = (const char*)g_hb[t & 1];
#pragma unroll
        for (int i = 0; i < 16; i++) {
            int f = tid + i * 256;
            int arr = f >> 11;
            int rem = f & 2047;
            int row = rem >> 7;
            int j = rem & 127;
            uint32_t s = smb + (arr ? SM_HL : SM_HH) + row * WROWB + j * 16;
            asm volatile("cp.async.cg.shared.global [%0], [%1], 16;"
                         :: "r"(s), "l"(srcb + (size_t)f * 16));
        }
        asm volatile("cp.async.commit_group;");
        asm volatile("cp.async.wait_group 0;");
        __syncthreads();

        float acc[2][4] = {{0.f, 0.f, 0.f, 0.f}, {0.f, 0.f, 0.f, 0.f}};
#pragma unroll
        for (int kc = 0; kc < 16; kc++) {
            uint32_t koff = kq * 512 + kc * 32;
            uint32_t bh[4], bl[4];
            ldsm4(bh, b_base + koff);
            ldsm4(bl, b_base + koff + (SM_HL - SM_HH));
#pragma unroll
            for (int nt = 0; nt < 2; nt++) {
                mma16816(acc[nt], wfh[kc], bh[nt * 2], bh[nt * 2 + 1]);
                mma16816(acc[nt], wfh[kc], bl[nt * 2], bl[nt * 2 + 1]);
                mma16816(acc[nt], wfl[kc], bh[nt * 2], bh[nt * 2 + 1]);
            }
        }

        if (kq > 0) {
            float* rb = &red[((mt * 3 + (kq - 1)) * 32 + lane) * 8];
            *(float4*)rb = *(float4*)acc[0];
            *(float4*)(rb + 4) = *(float4*)acc[1];
        }
        __syncthreads();
        if (kq == 0) {
#pragma unroll
            for (int w = 0; w < 3; w++) {
                const float* rb = &red[((mt * 3 + w) * 32 + lane) * 8];
                float4 r0 = *(const float4*)rb;
                float4 r1 = *(const float4*)(rb + 4);
                acc[0][0] += r0.x; acc[0][1] += r0.y;
                acc[0][2] += r0.z; acc[0][3] += r0.w;
                acc[1][0] += r1.x; acc[1][1] += r1.y;
                acc[1][2] += r1.z; acc[1][3] += r1.w;
            }
            int q = lane >> 2, p = lane & 3;
#pragma unroll
            for (int nt = 0; nt < 2; nt++) {
                int col = nt * 8 + p * 2;
                gsf[(mt * 16 + q) * 16 + col]     = acc[nt][0];
                gsf[(mt * 16 + q) * 16 + col + 1] = acc[nt][1];
                gsf[(mt * 16 + q + 8) * 16 + col]     = acc[nt][2];
                gsf[(mt * 16 + q + 8) * 16 + col + 1] = acc[nt][3];
            }
        }
        __syncthreads();

        // ---- gates; stage h (bf16 hi/lo) into smem ----
        float hval = 0.f, cval = 0.f;
        unsigned short hb_r = 0, lb_r = 0;
        if (tid < 128) {
            float gi = gsf[(ul * 4 + 0) * 16 + bb] + gx0;
            float gf = gsf[(ul * 4 + 1) * 16 + bb] + gx1;
            float gg2 = gsf[(ul * 4 + 2) * 16 + bb] + gx2;
            float go = gsf[(ul * 4 + 3) * 16 + bb] + gx3;
            float i_ = 1.f / (1.f + expf(-gi));
            float f_ = 1.f / (1.f + expf(-gf));
            float o_ = 1.f / (1.f + expf(-go));
            cval = f_ * cs[tid] + i_ * tanhf(gg2);
            hval = o_ * tanhf(cval);
            cs[tid] = cval;
            __nv_bfloat16 hb = __float2bfloat16(hval);
            __nv_bfloat16 lb = __float2bfloat16(hval - __bfloat162float(hb));
            hb_r = *(unsigned short*)&hb;
            lb_r = *(unsigned short*)&lb;
            stg[(0 * 16 + bb) * 8 + ul] = hb_r;
            stg[(1 * 16 + bb) * 8 + ul] = lb_r;
        }
        __syncthreads();

        // ---- warp 0: coalesced 16B publication of h, then release ----
        if (tid < 32) {
            int arr = tid >> 4, b2 = tid & 15;
            uint4 v = *(uint4*)&stg[(arr * 16 + b2) * 8];
            int nb = (t + 1) & 1;
            __stcg((uint4*)&g_hb[nb][arr][b2][bk * 8], v);
            __syncwarp();
            if (tid == 0)
                asm volatile("red.release.gpu.global.add.u32 [%0], 1;"
                             :: "l"(pbar) : "memory");
        }

        // ---- poller overlaps with off-critical-path stores ----
        if (tid == 128) {
            unsigned target = (unsigned)NBLK * (unsigned)(t + 1);
            unsigned v;
            do {
                asm volatile("ld.acquire.gpu.global.u32 %0, [%1];"
                             : "=r"(v) : "l"(pbar) : "memory");
            } while (v < target);
        } else if (tid < 128) {
            size_t hidx = ((size_t)(bb * TDEC + t)) * 1024 + u;
            g_hseq[hidx] = hval;
            c_hseq_hi[hidx] = *(__nv_bfloat16*)&hb_r;
            c_hseq_lo[hidx] = *(__nv_bfloat16*)&lb_r;
            out[((size_t)(bb * TDEC + t)) * 3072 + u] = hval;
            if (t == TDEC - 1) {
                size_t off = (size_t)BB * TDEC * 3072;
                out[off + bb * 1024 + u] = hval;
                out[off + BB * HH + bb * 1024 + u] = cval;
            }
        }
        __syncthreads();
    }
}

// ---------------- fused flash-style attention (bf16 hi/lo epilogue) ----------
__global__ void attn_kernel(const float* __restrict__ Q,
                            const float* __restrict__ Kb,
                            const float* __restrict__ Vb,
                            const unsigned char* __restrict__ mask,
                            __nv_bfloat16* __restrict__ Ohi,
                            __nv_bfloat16* __restrict__ Olo) {
    extern __shared__ float smf[];
    float* Qst = smf;
    float* Kst = Qst + 64 * 68;
    float* Vs  = Kst + 64 * 68;
    float* Pst = Vs + 64 * 68;
    float* madd = Pst + 64 * 68;

    int tid = threadIdx.x;
    int tx = tid & 15, ty = tid >> 4;
    int qt = blockIdx.x, hh = blockIdx.y, b = blockIdx.z;

    const float* Qbase = Q + ((size_t)(b * TDEC + qt * 64)) * EE + hh * DH;
#pragma unroll
    for (int i = 0; i < 4; i++) {
        int f4 = tid + i * 256;
        int q = f4 >> 4;
        int j = (f4 & 15) * 4;
        float4 v = *(const float4*)&Qbase[(size_t)q * EE + j];
        Qst[(j + 0) * 68 + q] = v.x; Qst[(j + 1) * 68 + q] = v.y;
        Qst[(j + 2) * 68 + q] = v.z; Qst[(j + 3) * 68 + q] = v.w;
    }

    unsigned long long o2[4][2];
    float mreg[4], lreg[4];
#pragma unroll
    for (int qq = 0; qq < 4; qq++) {
        mreg[qq] = -1e30f; lreg[qq] = 0.f;
        o2[qq][0] = 0ULL; o2[qq][1] = 0ULL;
    }

    for (int kb = 0; kb < TSRC / 64; kb++) {
        __syncthreads();
        const float* Kbase = Kb + ((size_t)(b * TSRC + kb * 64)) * EE + hh * DH;
        const float* Vbase = Vb + ((size_t)(b * TSRC + kb * 64)) * EE + hh * DH;
#pragma unroll
        for (int i = 0; i < 4; i++) {
            int f4 = tid + i * 256;
            int r = f4 >> 4;
            int j = (f4 & 15) * 4;
            float4 kv = *(const float4*)&Kbase[(size_t)r * EE + j];
            Kst[(j + 0) * 68 + r] = kv.x; Kst[(j + 1) * 68 + r] = kv.y;
            Kst[(j + 2) * 68 + r] = kv.z; Kst[(j + 3) * 68 + r] = kv.w;
            float4 vv = *(const float4*)&Vbase[(size_t)r * EE + j];
            *(float4*)&Vs[r * 68 + j] = vv;
        }
        if (tid < 64)
            madd[tid] = mask[b * TSRC + kb * 64 + tid] ? -1e9f : 0.f;
        __syncthreads();

        unsigned long long s2v[4][2];
#pragma unroll
        for (int qq = 0; qq < 4; qq++) { s2v[qq][0] = 0ULL; s2v[qq][1] = 0ULL; }

#pragma unroll 8
        for (int j = 0; j < 64; j++) {
            float4 qv = *(const float4*)&Qst[j * 68 + ty * 4];
            ulonglong2 kp = *(const ulonglong2*)&Kst[j * 68 + tx * 4];
            unsigned long long q2[4] = {pack2(qv.x, qv.x), pack2(qv.y, qv.y),
                                        pack2(qv.z, qv.z), pack2(qv.w, qv.w)};
#pragma unroll
            for (int qq = 0; qq < 4; qq++) {
                fma2(s2v[qq][0], q2[qq], kp.x);
                fma2(s2v[qq][1], q2[qq], kp.y);
            }
        }
        float kmadd[4];
#pragma unroll
        for (int kk = 0; kk < 4; kk++) kmadd[kk] = madd[tx * 4 + kk];

#pragma unroll
        for (int qq = 0; qq < 4; qq++) {
            float2 u0 = unpack2(s2v[qq][0]);
            float2 u1 = unpack2(s2v[qq][1]);
            float s[4] = {u0.x, u0.y, u1.x, u1.y};
#pragma unroll
            for (int kk = 0; kk < 4; kk++)
                s[kk] = s[kk] * 0.125f + kmadd[kk];
            float tmax = fmaxf(fmaxf(s[0], s[1]), fmaxf(s[2], s[3]));
#pragma unroll
            for (int off = 1; off < 16; off <<= 1)
                tmax = fmaxf(tmax, __shfl_xor_sync(0xffffffffu, tmax, off));
            float mnew = fmaxf(mreg[qq], tmax);
            float scale = expf(mreg[qq] - mnew);
            float psum = 0.f;
#pragma unroll
            for (int kk = 0; kk < 4; kk++) {
                float p = expf(s[kk] - mnew);
                Pst[(tx * 4 + kk) * 68 + ty * 4 + qq] = p;
                psum += p;
            }
#pragma unroll
            for (int off = 1; off < 16; off <<= 1)
                psum += __shfl_xor_sync(0xffffffffu, psum, off);
            lreg[qq] = lreg[qq] * scale + psum;
            mreg[qq] = mnew;
            unsigned long long sc2 = pack2(scale, scale);
            mul2(o2[qq][0], sc2);
            mul2(o2[qq][1], sc2);
        }
        __syncthreads();

#pragma unroll 8
        for (int k = 0; k < 64; k++) {
            float4 pv = *(const float4*)&Pst[k * 68 + ty * 4];
            ulonglong2 vp = *(const ulonglong2*)&Vs[k * 68 + tx * 4];
            unsigned long long p2[4] = {pack2(pv.x, pv.x), pack2(pv.y, pv.y),
                                        pack2(pv.z, pv.z), pack2(pv.w, pv.w)};
#pragma unroll
            for (int qq = 0; qq < 4; qq++) {
                fma2(o2[qq][0], p2[qq], vp.x);
                fma2(o2[qq][1], p2[qq], vp.y);
            }
        }
    }

#pragma unroll
    for (int qq = 0; qq < 4; qq++) {
        float inv = 1.f / lreg[qq];
        int q = ty * 4 + qq;
        float2 v0 = unpack2(o2[qq][0]);
        float2 v1 = unpack2(o2[qq][1]);
        float r[4] = {v0.x * inv, v0.y * inv, v1.x * inv, v1.y * inv};
        unsigned short hs[4], ls[4];
#pragma unroll
        for (int j = 0; j < 4; j++) {
            __nv_bfloat16 hb = __float2bfloat16(r[j]);
            __nv_bfloat16 lb = __float2bfloat16(r[j] - __bfloat162float(hb));
            hs[j] = *(unsigned short*)&hb;
            ls[j] = *(unsigned short*)&lb;
        }
        size_t off = ((size_t)(b * TDEC + qt * 64 + q)) * EE + hh * DH + tx * 4;
        *(ushort4*)&Ohi[off] = make_ushort4(hs[0], hs[1], hs[2], hs[3]);
        *(ushort4*)&Olo[off] = make_ushort4(ls[0], ls[1], ls[2], ls[3]);
    }
}

// ---------------- host orchestration -----------------------------------------
extern "C" void kernel_launch(void* const* d_in, const int* in_sizes, int n_in,
                              void* d_out, int out_size) {
    const float* X   = (const float*)d_in[0];
    const float* EI  = (const float*)d_in[1];
    const float* ET  = (const float*)d_in[2];
    const unsigned char* MI = (const unsigned char*)d_in[3];
    const unsigned char* MT = (const unsigned char*)d_in[4];
    const float* Wih = (const float*)d_in[5];
    const float* Whh = (const float*)d_in[6];
    const float* bih = (const float*)d_in[7];
    const float* bhh = (const float*)d_in[8];
    const float* Wq[2] = {(const float*)d_in[9],  (const float*)d_in[17]};
    const float* bq[2] = {(const float*)d_in[10], (const float*)d_in[18]};
    const float* Wk[2] = {(const float*)d_in[11], (const float*)d_in[19]};
    const float* bk[2] = {(const float*)d_in[12], (const float*)d_in[20]};
    const float* Wv[2] = {(const float*)d_in[13], (const float*)d_in[21]};
    const float* bv[2] = {(const float*)d_in[14], (const float*)d_in[22]};
    const float* Wo[2] = {(const float*)d_in[15], (const float*)d_in[23]};
    const float* bo[2] = {(const float*)d_in[16], (const float*)d_in[24]};
    float* out = (float*)d_out;

    float *p_gx, *p_hseq, *p_bias, *p_Kb, *p_Vb, *p_Kb2, *p_Vb2, *p_Qb, *p_Qb2;
    cudaGetSymbolAddress((void**)&p_gx, g_gx);
    cudaGetSymbolAddress((void**)&p_hseq, g_hseq);
    cudaGetSymbolAddress((void**)&p_bias, g_biascomb);
    cudaGetSymbolAddress((void**)&p_Kb, g_Kb);
    cudaGetSymbolAddress((void**)&p_Vb, g_Vb);
    cudaGetSymbolAddress((void**)&p_Kb2, g_Kb2);
    cudaGetSymbolAddress((void**)&p_Vb2, g_Vb2);
    cudaGetSymbolAddress((void**)&p_Qb, g_Qb);
    cudaGetSymbolAddress((void**)&p_Qb2, g_Qb2);
    __nv_bfloat16 *pA_h, *pA_l, *pWih_h, *pWih_l, *pHs_h, *pHs_l,
                  *pAO_h, *pAO_l, *pAO2_h, *pAO2_l,
                  *pE_h, *pE_l, *pW2_h, *pW2_l, *pW3_h, *pW3_l,
                  *pWq0_h, *pWq0_l, *pWq1_h, *pWq1_l,
                  *pWo0_h, *pWo0_l, *pWo1_h, *pWo1_l;
    cudaGetSymbolAddress((void**)&pA_h, c_bigA_hi);
    cudaGetSymbolAddress((void**)&pA_l, c_bigA_lo);
    cudaGetSymbolAddress((void**)&pWih_h, c_Wih_hi);
    cudaGetSymbolAddress((void**)&pWih_l, c_Wih_lo);
    cudaGetSymbolAddress((void**)&pHs_h, c_hseq_hi);
    cudaGetSymbolAddress((void**)&pHs_l, c_hseq_lo);
    cudaGetSymbolAddress((void**)&pAO_h, c_AO_hi);
    cudaGetSymbolAddress((void**)&pAO_l, c_AO_lo);
    cudaGetSymbolAddress((void**)&pAO2_h, c_AO2_hi);
    cudaGetSymbolAddress((void**)&pAO2_l, c_AO2_lo);
    cudaGetSymbolAddress((void**)&pE_h, c_enc_hi);
    cudaGetSymbolAddress((void**)&pE_l, c_enc_lo);
    cudaGetSymbolAddress((void**)&pW2_h, c_W2_hi);
    cudaGetSymbolAddress((void**)&pW2_l, c_W2_lo);
    cudaGetSymbolAddress((void**)&pW3_h, c_W3_hi);
    cudaGetSymbolAddress((void**)&pW3_l, c_W3_lo);
    cudaGetSymbolAddress((void**)&pWq0_h, c_Wq0_hi);
    cudaGetSymbolAddress((void**)&pWq0_l, c_Wq0_lo);
    cudaGetSymbolAddress((void**)&pWq1_h, c_Wq1_hi);
    cudaGetSymbolAddress((void**)&pWq1_l, c_Wq1_lo);
    cudaGetSymbolAddress((void**)&pWo0_h, c_Wo0_hi);
    cudaGetSymbolAddress((void**)&pWo0_l, c_Wo0_lo);
    cudaGetSymbolAddress((void**)&pWo1_h, c_Wo1_hi);
    cudaGetSymbolAddress((void**)&pWo1_l, c_Wo1_lo);

    const int ATTN_SMEM = (4 * 64 * 68 + 64) * sizeof(float);
    cudaFuncSetAttribute(attn_kernel,
                         cudaFuncAttributeMaxDynamicSharedMemorySize, ATTN_SMEM);
    cudaFuncSetAttribute(lstm_scan_kernel,
                         cudaFuncAttributeMaxDynamicSharedMemorySize, LSTM_SMEM_B);
    const int GEMM_SMEM = NSTAGE * STAGEB;
    cudaFuncSetAttribute(gemm_mma_kernel,
                         cudaFuncAttributeMaxDynamicSharedMemorySize, GEMM_SMEM);
    cudaFuncSetAttribute(gemm_xproj_kernel,
                         cudaFuncAttributeMaxDynamicSharedMemorySize, GEMM_SMEM);
    cudaFuncSetAttribute(gemm_dual_kernel,
                         cudaFuncAttributeMaxDynamicSharedMemorySize, GEMM_SMEM);

    static cudaStream_t s2 = nullptr;
    static cudaEvent_t eFork = nullptr, eKVi = nullptr, eW = nullptr,
                       eQ = nullptr, eDone = nullptr;
    if (!s2) {
        cudaStreamCreateWithFlags(&s2, cudaStreamNonBlocking);
        cudaEventCreateWithFlags(&eFork, cudaEventDisableTiming);
        cudaEventCreateWithFlags(&eKVi, cudaEventDisableTiming);
        cudaEventCreateWithFlags(&eW, cudaEventDisableTiming);
        cudaEventCreateWithFlags(&eQ, cudaEventDisableTiming);
        cudaEventCreateWithFlags(&eDone, cudaEventDisableTiming);
    }

    // ---- main stream chain ----
    conv_head_kernel<<<8192, 256>>>(X, pA_h, pA_l, Wih, pWih_h, pWih_l, bih, bhh);
    cudaEventRecord(eFork, 0);
    gemm_xproj_kernel<<<dim3(32, 32), 256, GEMM_SMEM>>>(
        pA_h, pA_l, pWih_h, pWih_l, p_bias, p_gx);
    lstm_scan_kernel<<<NBLK, 256, LSTM_SMEM_B>>>(Whh, out);

    // ---- side stream: KV chains + Q/O weight splits (overlap the scan) ----
    cudaStreamWaitEvent(s2, eFork, 0);
    conv_split_kernel<<<8192, 256, 0, s2>>>(EI, pE_h, pE_l, 1 << 21);
    conv_split_kernel<<<1024, 256, 0, s2>>>(Wk[0], pW2_h, pW2_l, 1 << 18);
    conv_split_kernel<<<1024, 256, 0, s2>>>(Wv[0], pW3_h, pW3_l, 1 << 18);
    gemm_dual_kernel<<<dim3(16, 64), 256, GEMM_SMEM, s2>>>(
        pE_h, pE_l, pW2_h, pW2_l, bk[0], p_Kb, pW3_h, pW3_l, bv[0], p_Vb);
    cudaEventRecord(eKVi, s2);
    conv_split_kernel<<<8192, 256, 0, s2>>>(ET, pE_h, pE_l, 1 << 21);
    conv_split_kernel<<<1024, 256, 0, s2>>>(Wk[1], pW2_h, pW2_l, 1 << 18);
    conv_split_kernel<<<1024, 256, 0, s2>>>(Wv[1], pW3_h, pW3_l, 1 << 18);
    gemm_dual_kernel<<<dim3(16, 64), 256, GEMM_SMEM, s2>>>(
        pE_h, pE_l, pW2_h, pW2_l, bk[1], p_Kb2, pW3_h, pW3_l, bv[1], p_Vb2);
    conv_split_kernel<<<1024, 256, 0, s2>>>(Wq[0], pWq0_h, pWq0_l, 1 << 18);
    conv_split_kernel<<<1024, 256, 0, s2>>>(Wq[1], pWq1_h, pWq1_l, 1 << 18);
    conv_split_kernel<<<1024, 256, 0, s2>>>(Wo[0], pWo0_h, pWo0_l, 1 << 18);
    conv_split_kernel<<<1024, 256, 0, s2>>>(Wo[1], pWo1_h, pWo1_l, 1 << 18);
    cudaEventRecord(eW, s2);

    // ---- main stream: fused Q projections (weights from s2) ----
    cudaStreamWaitEvent(0, eW, 0);
    gemm_dual_kernel<<<dim3(16, 32), 256, GEMM_SMEM>>>(
        pHs_h, pHs_l, pWq0_h, pWq0_l, bq[0], p_Qb,
        pWq1_h, pWq1_l, bq[1], p_Qb2);
    cudaEventRecord(eQ, 0);

    // ---- items chain on main; titles chain on s2 (parallel tail) ----
    cudaStreamWaitEvent(0, eKVi, 0);
    attn_kernel<<<dim3(4, 16, 16), 256, ATTN_SMEM>>>(
        p_Qb, p_Kb, p_Vb, MI, pAO_h, pAO_l);
    gemm_mma_kernel<<<dim3(8, 32), 256, GEMM_SMEM>>>(
        pAO_h, pAO_l, pWo0_h, pWo0_l, bo[0], p_hseq, HH,
        out + 1 * 1024, 3072);

    cudaStreamWaitEvent(s2, eQ, 0);
    attn_kernel<<<dim3(4, 16, 16), 256, ATTN_SMEM, s2>>>(
        p_Qb2, p_Kb2, p_Vb2, MT, pAO2_h, pAO2_l);
    gemm_mma_kernel<<<dim3(8, 32), 256, GEMM_SMEM, s2>>>(
        pAO2_h, pAO2_l, pWo1_h, pWo1_l, bo[1], p_hseq, HH,
        out + 2 * 1024, 3072);
    cudaEventRecord(eDone, s2);

    cudaStreamWaitEvent(0, eDone, 0);
}

// round 17
// speedup vs baseline: 1.0189x; 1.0189x over previous
#include <cuda_runtime.h>
#include <cuda_bf16.h>
#include <math.h>
#include <stdint.h>

#define BB 16
#define TDEC 256
#define TSRC 512
#define EE 1024
#define HH 1024
#define DH 64
#define NBLK 128

// ---------------- scratch (static device memory; no allocations) -------------
__device__ float g_gx[BB * TDEC * 4 * HH];
__device__ float g_hseq[BB * TDEC * HH];
__device__ __nv_bfloat16 g_hb[2][2][BB][HH];
__device__ float g_biascomb[4 * HH];
__device__ float g_Kb[BB * TSRC * EE];
__device__ float g_Vb[BB * TSRC * EE];
__device__ float g_Kb2[BB * TSRC * EE];
__device__ float g_Vb2[BB * TSRC * EE];
__device__ float g_Qb[BB * TDEC * EE];
__device__ float g_Qb2[BB * TDEC * EE];
__device__ unsigned g_bar;

// bf16 hi/lo split buffers (main stream)
__device__ __nv_bfloat16 c_bigA_hi[BB * TDEC * EE];
__device__ __nv_bfloat16 c_bigA_lo[BB * TDEC * EE];
__device__ __nv_bfloat16 c_Wih_hi[4 * HH * EE];
__device__ __nv_bfloat16 c_Wih_lo[4 * HH * EE];
__device__ __nv_bfloat16 c_hseq_hi[BB * TDEC * HH];
__device__ __nv_bfloat16 c_hseq_lo[BB * TDEC * HH];
__device__ __nv_bfloat16 c_AO_hi[BB * TDEC * EE];
__device__ __nv_bfloat16 c_AO_lo[BB * TDEC * EE];
__device__ __nv_bfloat16 c_AO2_hi[BB * TDEC * EE];
__device__ __nv_bfloat16 c_AO2_lo[BB * TDEC * EE];
// side-stream buffers
__device__ __nv_bfloat16 c_enc_hi[BB * TSRC * EE];
__device__ __nv_bfloat16 c_enc_lo[BB * TSRC * EE];
__device__ __nv_bfloat16 c_W2_hi[EE * EE];
__device__ __nv_bfloat16 c_W2_lo[EE * EE];
__device__ __nv_bfloat16 c_W3_hi[EE * EE];
__device__ __nv_bfloat16 c_W3_lo[EE * EE];
// dedicated Q/O weight splits (produced on s2 during the scan)
__device__ __nv_bfloat16 c_Wq0_hi[EE * EE];
__device__ __nv_bfloat16 c_Wq0_lo[EE * EE];
__device__ __nv_bfloat16 c_Wq1_hi[EE * EE];
__device__ __nv_bfloat16 c_Wq1_lo[EE * EE];
__device__ __nv_bfloat16 c_Wo0_hi[EE * EE];
__device__ __nv_bfloat16 c_Wo0_lo[EE * EE];
__device__ __nv_bfloat16 c_Wo1_hi[EE * EE];
__device__ __nv_bfloat16 c_Wo1_lo[EE * EE];

// ---------------- f32x2 packed-fp32 helpers ----------------------------------
__device__ __forceinline__ unsigned long long pack2(float a, float b) {
    unsigned long long r;
    asm("mov.b64 %0, {%1,%2};" : "=l"(r) : "f"(a), "f"(b));
    return r;
}
__device__ __forceinline__ void fma2(unsigned long long& d,
                                     unsigned long long a, unsigned long long b) {
    asm("fma.rn.f32x2 %0, %1, %2, %0;" : "+l"(d) : "l"(a), "l"(b));
}
__device__ __forceinline__ void mul2(unsigned long long& d, unsigned long long a) {
    asm("mul.rn.f32x2 %0, %0, %1;" : "+l"(d) : "l"(a));
}
__device__ __forceinline__ float2 unpack2(unsigned long long v) {
    float2 r;
    asm("mov.b64 {%0,%1}, %2;" : "=f"(r.x), "=f"(r.y) : "l"(v));
    return r;
}

__device__ __forceinline__ uint32_t smem_u32(const void* p) {
    uint32_t a;
    asm("{ .reg .u64 t; cvta.to.shared.u64 t, %1; cvt.u32.u64 %0, t; }"
        : "=r"(a) : "l"(p));
    return a;
}

// ---------------- mma helpers --------------------------------------------------
__device__ __forceinline__ void ldsm4(uint32_t* r, uint32_t addr) {
    asm volatile("ldmatrix.sync.aligned.m8n8.x4.shared.b16 {%0,%1,%2,%3}, [%4];"
                 : "=r"(r[0]), "=r"(r[1]), "=r"(r[2]), "=r"(r[3]) : "r"(addr));
}
__device__ __forceinline__ void mma16816(float* c, const uint32_t* a,
                                         uint32_t b0, uint32_t b1) {
    asm volatile(
        "mma.sync.aligned.m16n8k16.row.col.f32.bf16.bf16.f32 "
        "{%0,%1,%2,%3}, {%4,%5,%6,%7}, {%8,%9}, {%0,%1,%2,%3};"
        : "+f"(c[0]), "+f"(c[1]), "+f"(c[2]), "+f"(c[3])
        : "r"(a[0]), "r"(a[1]), "r"(a[2]), "r"(a[3]), "r"(b0), "r"(b1));
}

// ---------------- conv kernels -------------------------------------------------
__global__ void conv_split_kernel(const float* __restrict__ src,
                                  __nv_bfloat16* __restrict__ hi,
                                  __nv_bfloat16* __restrict__ lo, int n4) {
    int i = blockIdx.x * 256 + threadIdx.x;
    if (i >= n4) return;
    float4 v = ((const float4*)src)[i];
    float a[4] = {v.x, v.y, v.z, v.w};
    unsigned short h[4], l[4];
#pragma unroll
    for (int j = 0; j < 4; j++) {
        __nv_bfloat16 hb = __float2bfloat16(a[j]);
        __nv_bfloat16 lb = __float2bfloat16(a[j] - __bfloat162float(hb));
        h[j] = *(unsigned short*)&hb;
        l[j] = *(unsigned short*)&lb;
    }
    ((ushort4*)hi)[i] = make_ushort4(h[0], h[1], h[2], h[3]);
    ((ushort4*)lo)[i] = make_ushort4(l[0], l[1], l[2], l[3]);
}

// Wih split + fused bias_comb (b_ih + b_hh)
__global__ void conv_wih_bias_kernel(const float* __restrict__ src,
                                     __nv_bfloat16* __restrict__ hi,
                                     __nv_bfloat16* __restrict__ lo,
                                     const float* __restrict__ bih,
                                     const float* __restrict__ bhh) {
    int i = blockIdx.x * 256 + threadIdx.x;
    if (blockIdx.x < 16) {
        g_biascomb[i] = bih[i] + bhh[i];
    }
    float4 v = ((const float4*)src)[i];
    float a[4] = {v.x, v.y, v.z, v.w};
    unsigned short h[4], l[4];
#pragma unroll
    for (int j = 0; j < 4; j++) {
        __nv_bfloat16 hb = __float2bfloat16(a[j]);
        __nv_bfloat16 lb = __float2bfloat16(a[j] - __bfloat162float(hb));
        h[j] = *(unsigned short*)&hb;
        l[j] = *(unsigned short*)&lb;
    }
    ((ushort4*)hi)[i] = make_ushort4(h[0], h[1], h[2], h[3]);
    ((ushort4*)lo)[i] = make_ushort4(l[0], l[1], l[2], l[3]);
}

// ---------------- tensor-core GEMM via mma.sync (3-stage, 1 sync/chunk) -------
#define KC 64
#define MATB (128 * 72 * 2)
#define STAGEB (4 * MATB)
#define NSTAGE 3

__device__ __forceinline__ void gemm_body(
    const __nv_bfloat16* __restrict__ Ahi, const __nv_bfloat16* __restrict__ Alo,
    const __nv_bfloat16* __restrict__ Whi, const __nv_bfloat16* __restrict__ Wlo,
    const float* __restrict__ bias,
    const float* __restrict__ add, int addstride,
    float* __restrict__ out, int ostride, int m0, int n0, float* smf) {
    const uint32_t smb = smem_u32(smf);
    const int tid = threadIdx.x;
    const int warp = tid >> 5, lane = tid & 31;
    const int wm = warp >> 1, wn = warp & 1;
    const __nv_bfloat16* srcs[4] = {Ahi, Alo, Whi, Wlo};
    const int matoff[4] = {0, MATB, 2 * MATB, 3 * MATB};

    auto issue = [&](int c) {
        uint32_t sb = smb + (c % NSTAGE) * STAGEB;
#pragma unroll
        for (int i = 0; i < 16; i++) {
            int idx = tid + i * 256;
            int mat = idx >> 10;
            int rem = idx & 1023;
            int r = rem >> 3;
            int j = rem & 7;
            const __nv_bfloat16* g =
                srcs[mat] + (size_t)((mat < 2 ? m0 : n0) + r) * 1024 + c * KC + j * 8;
            uint32_t s = sb + matoff[mat] + r * 144 + j * 16;
            asm volatile("cp.async.cg.shared.global [%0], [%1], 16;"
                         :: "r"(s), "l"(g));
        }
        asm volatile("cp.async.commit_group;");
    };

    float acc[2][8][4];
#pragma unroll
    for (int mt = 0; mt < 2; mt++)
#pragma unroll
        for (int nt = 0; nt < 8; nt++)
#pragma unroll
            for (int e = 0; e < 4; e++) acc[mt][nt][e] = 0.f;

    const int a_row = lane & 15, a_kg = lane >> 4;
    const int b_row = (lane & 7) + ((lane & 16) >> 1);
    const int b_kg = (lane >> 3) & 1;

    issue(0);
    issue(1);
    for (int c = 0; c < 16; c++) {
        if (c < 15) {
            asm volatile("cp.async.wait_group 1;");
        } else {
            asm volatile("cp.async.wait_group 0;");
        }
        __syncthreads();

        if (c + 2 < 16) issue(c + 2);

        uint32_t st = smb + (c % NSTAGE) * STAGEB;
#pragma unroll
        for (int ks = 0; ks < 4; ks++) {
            uint32_t ah[2][4], al[2][4], wh[4][4], wl[4][4];
#pragma unroll
            for (int mt = 0; mt < 2; mt++) {
                uint32_t ra = st + (wm * 32 + mt * 16 + a_row) * 144 +
                              ks * 32 + a_kg * 16;
                ldsm4(ah[mt], ra);
                ldsm4(al[mt], ra + MATB);
            }
#pragma unroll
            for (int np = 0; np < 4; np++) {
                uint32_t rb = st + 2 * MATB + (wn * 64 + np * 16 + b_row) * 144 +
                              ks * 32 + b_kg * 16;
                ldsm4(wh[np], rb);
                ldsm4(wl[np], rb + MATB);
            }
#pragma unroll
            for (int mt = 0; mt < 2; mt++)
#pragma unroll
                for (int nt = 0; nt < 8; nt++) {
                    int np = nt >> 1, hf = (nt & 1) * 2;
                    mma16816(acc[mt][nt], ah[mt], wh[np][hf], wh[np][hf + 1]);
                    mma16816(acc[mt][nt], ah[mt], wl[np][hf], wl[np][hf + 1]);
                    mma16816(acc[mt][nt], al[mt], wh[np][hf], wh[np][hf + 1]);
                }
        }
    }

    const int q = lane >> 2, p = lane & 3;
#pragma unroll
    for (int mt = 0; mt < 2; mt++) {
#pragma unroll
        for (int nt = 0; nt < 8; nt++) {
            int n = n0 + wn * 64 + nt * 8 + p * 2;
            float b0 = bias[n], b1 = bias[n + 1];
#pragma unroll
            for (int half = 0; half < 2; half++) {
                int m = m0 + wm * 32 + mt * 16 + q + half * 8;
                float2 r;
                r.x = acc[mt][nt][half * 2 + 0] + b0;
                r.y = acc[mt][nt][half * 2 + 1] + b1;
                if (add) {
                    const float* ap = &add[(size_t)m * addstride + n];
                    r.x += ap[0]; r.y += ap[1];
                }
                *(float2*)&out[(size_t)m * ostride + n] = r;
            }
        }
    }
}

__global__ void __launch_bounds__(256, 1)
gemm_mma_kernel(const __nv_bfloat16* __restrict__ Ahi,
                const __nv_bfloat16* __restrict__ Alo,
                const __nv_bfloat16* __restrict__ Whi,
                const __nv_bfloat16* __restrict__ Wlo,
                const float* __restrict__ bias,
                const float* __restrict__ add, int addstride,
                float* __restrict__ out, int ostride) {
    extern __shared__ float smf[];
    gemm_body(Ahi, Alo, Whi, Wlo, bias, add, addstride, out, ostride,
              blockIdx.y * 128, blockIdx.x * 128, smf);
}

__global__ void __launch_bounds__(256, 1)
gemm_xproj_kernel(const __nv_bfloat16* __restrict__ Ahi,
                  const __nv_bfloat16* __restrict__ Alo,
                  const __nv_bfloat16* __restrict__ Whi,
                  const __nv_bfloat16* __restrict__ Wlo,
                  const float* __restrict__ bias,
                  float* __restrict__ out) {
    extern __shared__ float smf[];
    if (blockIdx.x == 0 && blockIdx.y == 0) {
        for (int i = threadIdx.x; i < 8192; i += 256)
            ((uint4*)g_hb)[i] = make_uint4(0, 0, 0, 0);
        if (threadIdx.x == 0) g_bar = 0u;
    }
    gemm_body(Ahi, Alo, Whi, Wlo, bias, nullptr, 0, out, 4096,
              blockIdx.y * 128, blockIdx.x * 128, smf);
}

__global__ void __launch_bounds__(256, 1)
gemm_dual_kernel(const __nv_bfloat16* __restrict__ Ahi,
                 const __nv_bfloat16* __restrict__ Alo,
                 const __nv_bfloat16* __restrict__ W1hi,
                 const __nv_bfloat16* __restrict__ W1lo,
                 const float* __restrict__ b1, float* __restrict__ o1,
                 const __nv_bfloat16* __restrict__ W2hi,
                 const __nv_bfloat16* __restrict__ W2lo,
                 const float* __restrict__ b2, float* __restrict__ o2) {
    extern __shared__ float smf[];
    int bx = blockIdx.x;
    if (bx < 8)
        gemm_body(Ahi, Alo, W1hi, W1lo, b1, nullptr, 0, o1, EE,
                  blockIdx.y * 128, bx * 128, smf);
    else
        gemm_body(Ahi, Alo, W2hi, W2lo, b2, nullptr, 0, o2, EE,
                  blockIdx.y * 128, (bx - 8) * 128, smf);
}

// ---------------- persistent LSTM scan (round-15 proven form) -----------------
#define WROWB 2064
#define SM_WH 0
#define SM_WL 66048
#define SM_HH 132096
#define SM_HL 165120
#define SM_RED 198144
#define SM_GS 204288
#define SM_CS 206336
#define LSTM_SMEM_B 206848

__global__ void __launch_bounds__(256, 1) lstm_scan_kernel(
    const float* __restrict__ Whh, float* __restrict__ out) {
    extern __shared__ float smf[];
    char* smbyte = (char*)smf;
    const uint32_t smb = smem_u32(smf);
    float* red = (float*)(smbyte + SM_RED);
    float* gsf = (float*)(smbyte + SM_GS);
    float* cs  = (float*)(smbyte + SM_CS);

    const int tid = threadIdx.x;
    const int bk = blockIdx.x;
    const int warp = tid >> 5, lane = tid & 31;
    const int mt = warp >> 2, kq = warp & 3;
    unsigned* pbar = &g_bar;

    for (int idx = tid; idx < 32 * 1024; idx += 256) {
        int r = idx >> 10, k = idx & 1023;
        int grow = (r & 3) * 1024 + bk * 8 + (r >> 2);
        float w = Whh[(size_t)grow * 1024 + k];
        __nv_bfloat16 hb = __float2bfloat16(w);
        __nv_bfloat16 lb = __float2bfloat16(w - __bfloat162float(hb));
        ((__nv_bfloat16*)(smbyte + SM_WH))[r * 1032 + k] = hb;
        ((__nv_bfloat16*)(smbyte + SM_WL))[r * 1032 + k] = lb;
    }
    if (tid < 128) cs[tid] = 0.f;
    __syncthreads();

    const uint32_t a_base = smb + SM_WH +
        (mt * 16 + (lane & 15)) * WROWB + (lane >> 4) * 16;
    const uint32_t b_base = smb + SM_HH +
        ((lane & 7) + ((lane & 16) >> 1)) * WROWB + ((lane >> 3) & 1) * 16;

    uint32_t wfh[16][4], wfl[16][4];
#pragma unroll
    for (int kc = 0; kc < 16; kc++) {
        uint32_t koff = kq * 512 + kc * 32;
        ldsm4(wfh[kc], a_base + koff);
        ldsm4(wfl[kc], a_base + koff + (SM_WL - SM_WH));
    }

    const int ul = tid >> 4, bb = tid & 15;
    const int u = bk * 8 + ul;

    for (int t = 0; t < TDEC; t++) {
        float gx0 = 0.f, gx1 = 0.f, gx2 = 0.f, gx3 = 0.f;
        if (tid < 128) {
            size_t xb = ((size_t)(bb * TDEC + t)) * 4096 + u;
            gx0 = g_gx[xb];
            gx1 = g_gx[xb + 1024];
            gx2 = g_gx[xb + 2048];
            gx3 = g_gx[xb + 3072];
        }

        const char* srcb = (const char*)g_hb[t & 1];
#pragma unroll
        for (int i = 0; i < 16; i++) {
            int f = tid + i * 256;
            int arr = f >> 11;
            int rem = f & 2047;
            int row = rem >> 7;
            int j = rem & 127;
            uint32_t s = smb + (arr ? SM_HL : SM_HH) + row * WROWB + j * 16;
            asm volatile("cp.async.cg.shared.global [%0], [%1], 16;"
                         :: "r"(s), "l"(srcb + (size_t)f * 16));
        }
        asm volatile("cp.async.commit_group;");
        asm volatile("cp.async.wait_group 0;");
        __syncthreads();

        float acc[2][4] = {{0.f, 0.f, 0.f, 0.f}, {0.f, 0.f, 0.f, 0.f}};
#pragma unroll
        for (int kc = 0; kc < 16; kc++) {
            uint32_t koff = kq * 512 + kc * 32;
            uint32_t bh[4], bl[4];
            ldsm4(bh, b_base + koff);
            ldsm4(bl, b_base + koff + (SM_HL - SM_HH));
#pragma unroll
            for (int nt = 0; nt < 2; nt++) {
                mma16816(acc[nt], wfh[kc], bh[nt * 2], bh[nt * 2 + 1]);
                mma16816(acc[nt], wfh[kc], bl[nt * 2], bl[nt * 2 + 1]);
                mma16816(acc[nt], wfl[kc], bh[nt * 2], bh[nt * 2 + 1]);
            }
        }

        if (kq > 0) {
            float* rb = &red[((mt * 3 + (kq - 1)) * 32 + lane) * 8];
            *(float4*)rb = *(float4*)acc[0];
            *(float4*)(rb + 4) = *(float4*)acc[1];
        }
        __syncthreads();
        if (kq == 0) {
#pragma unroll
            for (int w = 0; w < 3; w++) {
                const float* rb = &red[((mt * 3 + w) * 32 + lane) * 8];
                float4 r0 = *(const float4*)rb;
                float4 r1 = *(const float4*)(rb + 4);
                acc[0][0] += r0.x; acc[0][1] += r0.y;
                acc[0][2] += r0.z; acc[0][3] += r0.w;
                acc[1][0] += r1.x; acc[1][1] += r1.y;
                acc[1][2] += r1.z; acc[1][3] += r1.w;
            }
            int q = lane >> 2, p = lane & 3;
#pragma unroll
            for (int nt = 0; nt < 2; nt++) {
                int col = nt * 8 + p * 2;
                gsf[(mt * 16 + q) * 16 + col]     = acc[nt][0];
                gsf[(mt * 16 + q) * 16 + col + 1] = acc[nt][1];
                gsf[(mt * 16 + q + 8) * 16 + col]     = acc[nt][2];
                gsf[(mt * 16 + q + 8) * 16 + col + 1] = acc[nt][3];
            }
        }
        __syncthreads();

        // ---- gates; publish ONLY g_hb before the barrier arrival ----
        float hval = 0.f, cval = 0.f;
        if (tid < 128) {
            float gi = gsf[(ul * 4 + 0) * 16 + bb] + gx0;
            float gf = gsf[(ul * 4 + 1) * 16 + bb] + gx1;
            float gg2 = gsf[(ul * 4 + 2) * 16 + bb] + gx2;
            float go = gsf[(ul * 4 + 3) * 16 + bb] + gx3;
            float i_ = 1.f / (1.f + expf(-gi));
            float f_ = 1.f / (1.f + expf(-gf));
            float o_ = 1.f / (1.f + expf(-go));
            cval = f_ * cs[tid] + i_ * tanhf(gg2);
            hval = o_ * tanhf(cval);
            cs[tid] = cval;
            __nv_bfloat16 hb = __float2bfloat16(hval);
            __nv_bfloat16 lb = __float2bfloat16(hval - __bfloat162float(hb));
            int nb = (t + 1) & 1;
            __stcg(&g_hb[nb][0][bb][u], hb);
            __stcg(&g_hb[nb][1][bb][u], lb);
        }

        __syncthreads();
        if (tid == 0) {
            asm volatile("red.release.gpu.global.add.u32 [%0], 1;"
                         :: "l"(pbar) : "memory");
        }

        // ---- non-shared stores off the critical path ----
        if (tid < 128) {
            __nv_bfloat16 hb = __float2bfloat16(hval);
            __nv_bfloat16 lb = __float2bfloat16(hval - __bfloat162float(hb));
            size_t hidx = ((size_t)(bb * TDEC + t)) * 1024 + u;
            g_hseq[hidx] = hval;
            c_hseq_hi[hidx] = hb;
            c_hseq_lo[hidx] = lb;
            out[((size_t)(bb * TDEC + t)) * 3072 + u] = hval;
            if (t == TDEC - 1) {
                size_t off = (size_t)BB * TDEC * 3072;
                out[off + bb * 1024 + u] = hval;
                out[off + BB * HH + bb * 1024 + u] = cval;
            }
        }

        if (tid == 0) {
            unsigned target = (unsigned)NBLK * (unsigned)(t + 1);
            unsigned v;
            do {
                asm volatile("ld.acquire.gpu.global.u32 %0, [%1];"
                             : "=r"(v) : "l"(pbar) : "memory");
            } while (v < target);
        }
        __syncthreads();
    }
}

// ---------------- fused flash-style attention (8q x 4k, 128-row q-tile) -------
// grid (2, 16, 16); 256 threads: tx=tid&15 (4 k), ty=tid>>4 (8 q).
__global__ void attn_kernel(const float* __restrict__ Q,
                            const float* __restrict__ Kb,
                            const float* __restrict__ Vb,
                            const unsigned char* __restrict__ mask,
                            __nv_bfloat16* __restrict__ Ohi,
                            __nv_bfloat16* __restrict__ Olo) {
    extern __shared__ float smf[];
    float* Qst = smf;                   // [64 j][132 q]
    float* Kst = Qst + 64 * 132;        // [64 j][68 k]
    float* Vs  = Kst + 64 * 68;         // [64 k][68 d]
    float* Pst = Vs + 64 * 68;          // [64 k][132 q]
    float* madd = Pst + 64 * 132;       // [64]

    int tid = threadIdx.x;
    int tx = tid & 15, ty = tid >> 4;
    int qt = blockIdx.x, hh = blockIdx.y, b = blockIdx.z;

    const float* Qbase = Q + ((size_t)(b * TDEC + qt * 128)) * EE + hh * DH;
#pragma unroll
    for (int i = 0; i < 8; i++) {
        int f4 = tid + i * 256;         // 0..2047
        int q = f4 >> 4;                // 0..127
        int j = (f4 & 15) * 4;
        float4 v = *(const float4*)&Qbase[(size_t)q * EE + j];
        Qst[(j + 0) * 132 + q] = v.x; Qst[(j + 1) * 132 + q] = v.y;
        Qst[(j + 2) * 132 + q] = v.z; Qst[(j + 3) * 132 + q] = v.w;
    }

    unsigned long long o2[8][2];
    float mreg[8], lreg[8];
#pragma unroll
    for (int qq = 0; qq < 8; qq++) {
        mreg[qq] = -1e30f; lreg[qq] = 0.f;
        o2[qq][0] = 0ULL; o2[qq][1] = 0ULL;
    }

    for (int kb = 0; kb < TSRC / 64; kb++) {
        __syncthreads();
        const float* Kbase = Kb + ((size_t)(b * TSRC + kb * 64)) * EE + hh * DH;
        const float* Vbase = Vb + ((size_t)(b * TSRC + kb * 64)) * EE + hh * DH;
#pragma unroll
        for (int i = 0; i < 4; i++) {
            int f4 = tid + i * 256;
            int r = f4 >> 4;
            int j = (f4 & 15) * 4;
            float4 kv = *(const float4*)&Kbase[(size_t)r * EE + j];
            Kst[(j + 0) * 68 + r] = kv.x; Kst[(j + 1) * 68 + r] = kv.y;
            Kst[(j + 2) * 68 + r] = kv.z; Kst[(j + 3) * 68 + r] = kv.w;
            float4 vv = *(const float4*)&Vbase[(size_t)r * EE + j];
            *(float4*)&Vs[r * 68 + j] = vv;
        }
        if (tid < 64)
            madd[tid] = mask[b * TSRC + kb * 64 + tid] ? -1e9f : 0.f;
        __syncthreads();

        unsigned long long s2v[8][2];
#pragma unroll
        for (int qq = 0; qq < 8; qq++) { s2v[qq][0] = 0ULL; s2v[qq][1] = 0ULL; }

#pragma unroll 4
        for (int j = 0; j < 64; j++) {
            float4 qv0 = *(const float4*)&Qst[j * 132 + ty * 8];
            float4 qv1 = *(const float4*)&Qst[j * 132 + ty * 8 + 4];
            ulonglong2 kp = *(const ulonglong2*)&Kst[j * 68 + tx * 4];
            unsigned long long q2[8] = {
                pack2(qv0.x, qv0.x), pack2(qv0.y, qv0.y),
                pack2(qv0.z, qv0.z), pack2(qv0.w, qv0.w),
                pack2(qv1.x, qv1.x), pack2(qv1.y, qv1.y),
                pack2(qv1.z, qv1.z), pack2(qv1.w, qv1.w)};
#pragma unroll
            for (int qq = 0; qq < 8; qq++) {
                fma2(s2v[qq][0], q2[qq], kp.x);
                fma2(s2v[qq][1], q2[qq], kp.y);
            }
        }
        float kmadd[4];
#pragma unroll
        for (int kk = 0; kk < 4; kk++) kmadd[kk] = madd[tx * 4 + kk];

#pragma unroll
        for (int qq = 0; qq < 8; qq++) {
            float2 u0 = unpack2(s2v[qq][0]);
            float2 u1 = unpack2(s2v[qq][1]);
            float s[4] = {u0.x, u0.y, u1.x, u1.y};
#pragma unroll
            for (int kk = 0; kk < 4; kk++)
                s[kk] = s[kk] * 0.125f + kmadd[kk];
            float tmax = fmaxf(fmaxf(s[0], s[1]), fmaxf(s[2], s[3]));
#pragma unroll
            for (int off = 1; off < 16; off <<= 1)
                tmax = fmaxf(tmax, __shfl_xor_sync(0xffffffffu, tmax, off));
            float mnew = fmaxf(mreg[qq], tmax);
            float scale = expf(mreg[qq] - mnew);
            float psum = 0.f;
#pragma unroll
            for (int kk = 0; kk < 4; kk++) {
                float p = expf(s[kk] - mnew);
                Pst[(tx * 4 + kk) * 132 + ty * 8 + qq] = p;
                psum += p;
            }
#pragma unroll
            for (int off = 1; off < 16; off <<= 1)
                psum += __shfl_xor_sync(0xffffffffu, psum, off);
            lreg[qq] = lreg[qq] * scale + psum;
            mreg[qq] = mnew;
            unsigned long long sc2 = pack2(scale, scale);
            mul2(o2[qq][0], sc2);
            mul2(o2[qq][1], sc2);
        }
        __syncthreads();

#pragma unroll 4
        for (int k = 0; k < 64; k++) {
            float4 pv0 = *(const float4*)&Pst[k * 132 + ty * 8];
            float4 pv1 = *(const float4*)&Pst[k * 132 + ty * 8 + 4];
            ulonglong2 vp = *(const ulonglong2*)&Vs[k * 68 + tx * 4];
            unsigned long long p2[8] = {
                pack2(pv0.x, pv0.x), pack2(pv0.y, pv0.y),
                pack2(pv0.z, pv0.z), pack2(pv0.w, pv0.w),
                pack2(pv1.x, pv1.x), pack2(pv1.y, pv1.y),
                pack2(pv1.z, pv1.z), pack2(pv1.w, pv1.w)};
#pragma unroll
            for (int qq = 0; qq < 8; qq++) {
                fma2(o2[qq][0], p2[qq], vp.x);
                fma2(o2[qq][1], p2[qq], vp.y);
            }
        }
    }

#pragma unroll
    for (int qq = 0; qq < 8; qq++) {
        float inv = 1.f / lreg[qq];
        int q = ty * 8 + qq;
        float2 v0 = unpack2(o2[qq][0]);
        float2 v1 = unpack2(o2[qq][1]);
        float r[4] = {v0.x * inv, v0.y * inv, v1.x * inv, v1.y * inv};
        unsigned short hs[4], ls[4];
#pragma unroll
        for (int j = 0; j < 4; j++) {
            __nv_bfloat16 hb = __float2bfloat16(r[j]);
            __nv_bfloat16 lb = __float2bfloat16(r[j] - __bfloat162float(hb));
            hs[j] = *(unsigned short*)&hb;
            ls[j] = *(unsigned short*)&lb;
        }
        size_t off = ((size_t)(b * TDEC + qt * 128 + q)) * EE + hh * DH + tx * 4;
        *(ushort4*)&Ohi[off] = make_ushort4(hs[0], hs[1], hs[2], hs[3]);
        *(ushort4*)&Olo[off] = make_ushort4(ls[0], ls[1], ls[2], ls[3]);
    }
}

// ---------------- host orchestration -----------------------------------------
extern "C" void kernel_launch(void* const* d_in, const int* in_sizes, int n_in,
                              void* d_out, int out_size) {
    const float* X   = (const float*)d_in[0];
    const float* EI  = (const float*)d_in[1];
    const float* ET  = (const float*)d_in[2];
    const unsigned char* MI = (const unsigned char*)d_in[3];
    const unsigned char* MT = (const unsigned char*)d_in[4];
    const float* Wih = (const float*)d_in[5];
    const float* Whh = (const float*)d_in[6];
    const float* bih = (const float*)d_in[7];
    const float* bhh = (const float*)d_in[8];
    const float* Wq[2] = {(const float*)d_in[9],  (const float*)d_in[17]};
    const float* bq[2] = {(const float*)d_in[10], (const float*)d_in[18]};
    const float* Wk[2] = {(const float*)d_in[11], (const float*)d_in[19]};
    const float* bk[2] = {(const float*)d_in[12], (const float*)d_in[20]};
    const float* Wv[2] = {(const float*)d_in[13], (const float*)d_in[21]};
    const float* bv[2] = {(const float*)d_in[14], (const float*)d_in[22]};
    const float* Wo[2] = {(const float*)d_in[15], (const float*)d_in[23]};
    const float* bo[2] = {(const float*)d_in[16], (const float*)d_in[24]};
    float* out = (float*)d_out;

    float *p_gx, *p_hseq, *p_bias, *p_Kb, *p_Vb, *p_Kb2, *p_Vb2, *p_Qb, *p_Qb2;
    cudaGetSymbolAddress((void**)&p_gx, g_gx);
    cudaGetSymbolAddress((void**)&p_hseq, g_hseq);
    cudaGetSymbolAddress((void**)&p_bias, g_biascomb);
    cudaGetSymbolAddress((void**)&p_Kb, g_Kb);
    cudaGetSymbolAddress((void**)&p_Vb, g_Vb);
    cudaGetSymbolAddress((void**)&p_Kb2, g_Kb2);
    cudaGetSymbolAddress((void**)&p_Vb2, g_Vb2);
    cudaGetSymbolAddress((void**)&p_Qb, g_Qb);
    cudaGetSymbolAddress((void**)&p_Qb2, g_Qb2);
    __nv_bfloat16 *pA_h, *pA_l, *pWih_h, *pWih_l, *pHs_h, *pHs_l,
                  *pAO_h, *pAO_l, *pAO2_h, *pAO2_l,
                  *pE_h, *pE_l, *pW2_h, *pW2_l, *pW3_h, *pW3_l,
                  *pWq0_h, *pWq0_l, *pWq1_h, *pWq1_l,
                  *pWo0_h, *pWo0_l, *pWo1_h, *pWo1_l;
    cudaGetSymbolAddress((void**)&pA_h, c_bigA_hi);
    cudaGetSymbolAddress((void**)&pA_l, c_bigA_lo);
    cudaGetSymbolAddress((void**)&pWih_h, c_Wih_hi);
    cudaGetSymbolAddress((void**)&pWih_l, c_Wih_lo);
    cudaGetSymbolAddress((void**)&pHs_h, c_hseq_hi);
    cudaGetSymbolAddress((void**)&pHs_l, c_hseq_lo);
    cudaGetSymbolAddress((void**)&pAO_h, c_AO_hi);
    cudaGetSymbolAddress((void**)&pAO_l, c_AO_lo);
    cudaGetSymbolAddress((void**)&pAO2_h, c_AO2_hi);
    cudaGetSymbolAddress((void**)&pAO2_l, c_AO2_lo);
    cudaGetSymbolAddress((void**)&pE_h, c_enc_hi);
    cudaGetSymbolAddress((void**)&pE_l, c_enc_lo);
    cudaGetSymbolAddress((void**)&pW2_h, c_W2_hi);
    cudaGetSymbolAddress((void**)&pW2_l, c_W2_lo);
    cudaGetSymbolAddress((void**)&pW3_h, c_W3_hi);
    cudaGetSymbolAddress((void**)&pW3_l, c_W3_lo);
    cudaGetSymbolAddress((void**)&pWq0_h, c_Wq0_hi);
    cudaGetSymbolAddress((void**)&pWq0_l, c_Wq0_lo);
    cudaGetSymbolAddress((void**)&pWq1_h, c_Wq1_hi);
    cudaGetSymbolAddress((void**)&pWq1_l, c_Wq1_lo);
    cudaGetSymbolAddress((void**)&pWo0_h, c_Wo0_hi);
    cudaGetSymbolAddress((void**)&pWo0_l, c_Wo0_lo);
    cudaGetSymbolAddress((void**)&pWo1_h, c_Wo1_hi);
    cudaGetSymbolAddress((void**)&pWo1_l, c_Wo1_lo);

    const int ATTN_SMEM = (64 * 132 + 64 * 68 + 64 * 68 + 64 * 132 + 64) *
                          (int)sizeof(float);   // 102656 B
    cudaFuncSetAttribute(attn_kernel,
                         cudaFuncAttributeMaxDynamicSharedMemorySize, ATTN_SMEM);
    cudaFuncSetAttribute(lstm_scan_kernel,
                         cudaFuncAttributeMaxDynamicSharedMemorySize, LSTM_SMEM_B);
    const int GEMM_SMEM = NSTAGE * STAGEB;
    cudaFuncSetAttribute(gemm_mma_kernel,
                         cudaFuncAttributeMaxDynamicSharedMemorySize, GEMM_SMEM);
    cudaFuncSetAttribute(gemm_xproj_kernel,
                         cudaFuncAttributeMaxDynamicSharedMemorySize, GEMM_SMEM);
    cudaFuncSetAttribute(gemm_dual_kernel,
                         cudaFuncAttributeMaxDynamicSharedMemorySize, GEMM_SMEM);

    static cudaStream_t s2 = nullptr;
    static cudaEvent_t eFork = nullptr, eKVi = nullptr, eW = nullptr,
                       eQ = nullptr, eDone = nullptr;
    if (!s2) {
        cudaStreamCreateWithFlags(&s2, cudaStreamNonBlocking);
        cudaEventCreateWithFlags(&eFork, cudaEventDisableTiming);
        cudaEventCreateWithFlags(&eKVi, cudaEventDisableTiming);
        cudaEventCreateWithFlags(&eW, cudaEventDisableTiming);
        cudaEventCreateWithFlags(&eQ, cudaEventDisableTiming);
        cudaEventCreateWithFlags(&eDone, cudaEventDisableTiming);
    }

    // ---- main stream chain (round-15 proven structure) ----
    conv_split_kernel<<<4096, 256>>>(X, pA_h, pA_l, 1 << 20);
    conv_wih_bias_kernel<<<4096, 256>>>(Wih, pWih_h, pWih_l, bih, bhh);
    cudaEventRecord(eFork, 0);
    gemm_xproj_kernel<<<dim3(32, 32), 256, GEMM_SMEM>>>(
        pA_h, pA_l, pWih_h, pWih_l, p_bias, p_gx);
    lstm_scan_kernel<<<NBLK, 256, LSTM_SMEM_B>>>(Whh, out);

    // ---- side stream: KV chains + Q/O weight splits (overlap the scan) ----
    cudaStreamWaitEvent(s2, eFork, 0);
    conv_split_kernel<<<8192, 256, 0, s2>>>(EI, pE_h, pE_l, 1 << 21);
    conv_split_kernel<<<1024, 256, 0, s2>>>(Wk[0], pW2_h, pW2_l, 1 << 18);
    conv_split_kernel<<<1024, 256, 0, s2>>>(Wv[0], pW3_h, pW3_l, 1 << 18);
    gemm_dual_kernel<<<dim3(16, 64), 256, GEMM_SMEM, s2>>>(
        pE_h, pE_l, pW2_h, pW2_l, bk[0], p_Kb, pW3_h, pW3_l, bv[0], p_Vb);
    cudaEventRecord(eKVi, s2);
    conv_split_kernel<<<8192, 256, 0, s2>>>(ET, pE_h, pE_l, 1 << 21);
    conv_split_kernel<<<1024, 256, 0, s2>>>(Wk[1], pW2_h, pW2_l, 1 << 18);
    conv_split_kernel<<<1024, 256, 0, s2>>>(Wv[1], pW3_h, pW3_l, 1 << 18);
    gemm_dual_kernel<<<dim3(16, 64), 256, GEMM_SMEM, s2>>>(
        pE_h, pE_l, pW2_h, pW2_l, bk[1], p_Kb2, pW3_h, pW3_l, bv[1], p_Vb2);
    conv_split_kernel<<<1024, 256, 0, s2>>>(Wq[0], pWq0_h, pWq0_l, 1 << 18);
    conv_split_kernel<<<1024, 256, 0, s2>>>(Wq[1], pWq1_h, pWq1_l, 1 << 18);
    conv_split_kernel<<<1024, 256, 0, s2>>>(Wo[0], pWo0_h, pWo0_l, 1 << 18);
    conv_split_kernel<<<1024, 256, 0, s2>>>(Wo[1], pWo1_h, pWo1_l, 1 << 18);
    cudaEventRecord(eW, s2);

    // ---- main stream: fused Q projections (weights from s2) ----
    cudaStreamWaitEvent(0, eW, 0);
    gemm_dual_kernel<<<dim3(16, 32), 256, GEMM_SMEM>>>(
        pHs_h, pHs_l, pWq0_h, pWq0_l, bq[0], p_Qb,
        pWq1_h, pWq1_l, bq[1], p_Qb2);
    cudaEventRecord(eQ, 0);

    // ---- items chain on main; titles chain on s2 (parallel tail) ----
    cudaStreamWaitEvent(0, eKVi, 0);
    attn_kernel<<<dim3(2, 16, 16), 256, ATTN_SMEM>>>(
        p_Qb, p_Kb, p_Vb, MI, pAO_h, pAO_l);
    gemm_mma_kernel<<<dim3(8, 32), 256, GEMM_SMEM>>>(
        pAO_h, pAO_l, pWo0_h, pWo0_l, bo[0], p_hseq, HH,
        out + 1 * 1024, 3072);

    cudaStreamWaitEvent(s2, eQ, 0);
    attn_kernel<<<dim3(2, 16, 16), 256, ATTN_SMEM, s2>>>(
        p_Qb2, p_Kb2, p_Vb2, MT, pAO2_h, pAO2_l);
    gemm_mma_kernel<<<dim3(8, 32), 256, GEMM_SMEM, s2>>>(
        pAO2_h, pAO2_l, pWo1_h, pWo1_l, bo[1], p_hseq, HH,
        out + 2 * 1024, 3072);
    cudaEventRecord(eDone, s2);

    cudaStreamWaitEvent(0, eDone, 0);
}